// round 1
// baseline (speedup 1.0000x reference)
#include <cuda_runtime.h>
#include <math.h>

// Problem constants
#define BB   256
#define TT   512
#define DD   128
#define TMDIM 510           // T - LAGS
#define FF   385            // H + L*D + 1
#define RES_SIZE (256*510*128)

// Scratch (device globals; no allocation allowed)
__device__ float g_Wst[256*128];   // stacked Wy, K-major: g_Wst[kk*128+d] = Wg[d*385+128+kk]
__device__ float g_wx[128];        // Wg[d*385+384]
__device__ float g_cbuf[256*128];  // c[b,d] = (emb @ We^T)[b,d] + bg[d]

// ---------------------------------------------------------------------------
// prep: transpose weights, extract wx, compute logdet output
// grid: 129 blocks x 256 threads
// ---------------------------------------------------------------------------
__global__ void prep_kernel(const float* __restrict__ Wg, float* __restrict__ out)
{
    if (blockIdx.x < 128) {
        int idx = blockIdx.x * 256 + threadIdx.x;   // 0..32767
        int d  = idx & 127;
        int kk = idx >> 7;
        g_Wst[idx] = Wg[d * FF + 128 + kk];
    } else {
        __shared__ float red[128];
        __shared__ float tot;
        int t = threadIdx.x;
        if (t < 128) {
            float w = Wg[t * FF + 384];
            g_wx[t] = w;
            red[t] = logf(fabsf(w));
        }
        __syncthreads();
        #pragma unroll
        for (int s = 64; s > 0; s >>= 1) {
            if (t < s) red[t] += red[t + s];
            __syncthreads();
        }
        if (t == 0) tot = red[0] * 510.0f;
        __syncthreads();
        out[RES_SIZE + t] = tot;   // t = 0..255 -> one value per batch row
    }
}

// ---------------------------------------------------------------------------
// mlp: per-batch-row 3-layer MLP (leaky_relu 0.2) + c = emb @ We^T + bg
// grid: 256 blocks x 128 threads, dyn smem = (128*129 + 128)*4 bytes
// ---------------------------------------------------------------------------
__global__ void mlp_kernel(const float* __restrict__ emb_in,
                           const float* __restrict__ W1, const float* __restrict__ b1,
                           const float* __restrict__ W2, const float* __restrict__ b2,
                           const float* __restrict__ W3, const float* __restrict__ b3,
                           const float* __restrict__ Wg, const float* __restrict__ bg)
{
    extern __shared__ float sm[];
    float* Wsm = sm;             // 128 rows, pitch 129 (conflict-free)
    float* es  = sm + 128*129;   // current activation vector (128)
    const int b = blockIdx.x;
    const int t = threadIdx.x;   // 0..127

    es[t] = emb_in[b * 128 + t];

    // ---- layer 1 ----
    #pragma unroll 4
    for (int i = 0; i < 128; i++) Wsm[i*129 + t] = W1[i*128 + t];
    __syncthreads();
    float acc = b1[t];
    #pragma unroll
    for (int k = 0; k < 128; k++) acc += es[k] * Wsm[t*129 + k];
    acc = (acc > 0.f) ? acc : 0.2f * acc;
    __syncthreads();
    es[t] = acc;

    // ---- layer 2 ----
    #pragma unroll 4
    for (int i = 0; i < 128; i++) Wsm[i*129 + t] = W2[i*128 + t];
    __syncthreads();
    acc = b2[t];
    #pragma unroll
    for (int k = 0; k < 128; k++) acc += es[k] * Wsm[t*129 + k];
    acc = (acc > 0.f) ? acc : 0.2f * acc;
    __syncthreads();
    es[t] = acc;

    // ---- layer 3 (no activation) ----
    #pragma unroll 4
    for (int i = 0; i < 128; i++) Wsm[i*129 + t] = W3[i*128 + t];
    __syncthreads();
    acc = b3[t];
    #pragma unroll
    for (int k = 0; k < 128; k++) acc += es[k] * Wsm[t*129 + k];
    __syncthreads();
    es[t] = acc;                 // emb row

    // ---- c = emb @ We^T + bg,  We[d,h] = Wg[d*385 + h] ----
    #pragma unroll 4
    for (int i = 0; i < 128; i++) Wsm[i*129 + t] = Wg[i*FF + t];
    __syncthreads();
    float c = bg[t];
    #pragma unroll
    for (int k = 0; k < 128; k++) c += es[k] * Wsm[t*129 + k];
    g_cbuf[b * 128 + t] = c;
}

// ---------------------------------------------------------------------------
// main GEMM: res[b,t,d] = c[b,d] + sum_k x[b,t,k]*Wy[d,k]
//                        + sum_k x[b,t+1,k]*Wy[d,128+k] + x[b,t+2,d]*wx[d]
// grid: 1024 blocks (b = blk>>2, t-tile = blk&3) x 256 threads
// dyn smem: Ws 256x128 (128 KB) + As 128x131 transposed x rows (65.5 KB)
// ---------------------------------------------------------------------------
__global__ void __launch_bounds__(256, 1)
main_kernel(const float* __restrict__ x, float* __restrict__ out)
{
    extern __shared__ float sm[];
    float* Ws = sm;                 // Ws[kk*128 + d], kk = 0..255
    float* As = sm + 256*128;       // As[k*131 + r] = x[b, t0+r, k], r = 0..129
    const int bid = blockIdx.x;
    const int b   = bid >> 2;
    const int t0  = (bid & 3) * 128;
    const int TMloc = min(128, TMDIM - t0);     // 128,128,128,126
    const int nrows = min(130, TT - t0);        // rows of x available
    const int tid = threadIdx.x;

    // stage weights (coalesced float4, conflict-free)
    {
        const float4* src = (const float4*)g_Wst;
        float4*       dst = (float4*)Ws;
        #pragma unroll
        for (int i = 0; i < 32; i++) dst[i*256 + tid] = src[i*256 + tid];
    }
    // stage x rows transposed: As[k][r]; pitch 131 (odd) -> conflict-free STS
    {
        const int k  = tid & 127;
        const int rr = tid >> 7;    // 0..1
        const float* xb = x + ((size_t)b * TT + t0) * DD;
        #pragma unroll
        for (int r0 = 0; r0 < 130; r0 += 2) {
            int r = r0 + rr;
            As[k*131 + r] = (r < nrows) ? xb[r*DD + k] : 0.0f;
        }
    }
    __syncthreads();

    const int tx = tid & 15, ty = tid >> 4;
    const int m0 = ty * 8, n0 = tx * 8;

    float acc[8][8];
    #pragma unroll
    for (int i = 0; i < 8; i++)
        #pragma unroll
        for (int j = 0; j < 8; j++) acc[i][j] = 0.f;

    // half 0: A rows m (x[t0+m]), Ws rows 0..127; half 1: A rows m+1, Ws rows 128..255
    #pragma unroll 1
    for (int half = 0; half < 2; half++) {
        const float* Wb = Ws + half * 128 * 128;
        const int    off = half;
        #pragma unroll 4
        for (int kk = 0; kk < 128; kk++) {
            float a[8];
            #pragma unroll
            for (int i = 0; i < 8; i++) a[i] = As[kk*131 + m0 + off + i];
            const float4 p = *(const float4*)(Wb + kk*128 + n0);
            const float4 q = *(const float4*)(Wb + kk*128 + n0 + 4);
            const float bf[8] = {p.x, p.y, p.z, p.w, q.x, q.y, q.z, q.w};
            #pragma unroll
            for (int i = 0; i < 8; i++)
                #pragma unroll
                for (int j = 0; j < 8; j++)
                    acc[i][j] += a[i] * bf[j];
        }
    }

    // epilogue: + c[b,d] + x[b,t+2,d]*wx[d]
    float cb[8], wv[8];
    #pragma unroll
    for (int j = 0; j < 8; j++) {
        cb[j] = g_cbuf[b * 128 + n0 + j];
        wv[j] = g_wx[n0 + j];
    }
    float* ob = out + ((size_t)b * TMDIM + t0) * DD;
    #pragma unroll
    for (int i = 0; i < 8; i++) {
        const int m = m0 + i;
        if (m < TMloc) {
            float r[8];
            #pragma unroll
            for (int j = 0; j < 8; j++) {
                const float xv = As[(n0 + j)*131 + m + 2];   // x[b, t0+m+2, n0+j]
                r[j] = acc[i][j] + cb[j] + xv * wv[j];
            }
            float4* op = (float4*)(ob + (size_t)m * DD + n0);
            op[0] = make_float4(r[0], r[1], r[2], r[3]);
            op[1] = make_float4(r[4], r[5], r[6], r[7]);
        }
    }
}

// ---------------------------------------------------------------------------
extern "C" void kernel_launch(void* const* d_in, const int* in_sizes, int n_in,
                              void* d_out, int out_size)
{
    const float* x   = (const float*)d_in[0];
    const float* emb = (const float*)d_in[1];
    const float* W1  = (const float*)d_in[2];
    const float* b1  = (const float*)d_in[3];
    const float* W2  = (const float*)d_in[4];
    const float* b2  = (const float*)d_in[5];
    const float* W3  = (const float*)d_in[6];
    const float* b3  = (const float*)d_in[7];
    const float* Wg  = (const float*)d_in[8];
    const float* bg  = (const float*)d_in[9];
    float* out = (float*)d_out;

    const int mlp_smem  = (128*129 + 128) * sizeof(float);        // 66560 B
    const int main_smem = (256*128 + 128*131) * sizeof(float);    // 198144 B
    cudaFuncSetAttribute(mlp_kernel,  cudaFuncAttributeMaxDynamicSharedMemorySize, mlp_smem);
    cudaFuncSetAttribute(main_kernel, cudaFuncAttributeMaxDynamicSharedMemorySize, main_smem);

    prep_kernel<<<129, 256>>>(Wg, out);
    mlp_kernel<<<256, 128, mlp_smem>>>(emb, W1, b1, W2, b2, W3, b3, Wg, bg);
    main_kernel<<<1024, 256, main_smem>>>(x, out);
}

// round 5
// speedup vs baseline: 1.3974x; 1.3974x over previous
#include <cuda_runtime.h>
#include <cuda_bf16.h>
#include <math.h>
#include <stdint.h>

// Problem constants
#define BB   256
#define TT   512
#define DD   128
#define TMDIM 510           // T - LAGS
#define FF   385            // H + L*D + 1
#define RES_SIZE (256*510*128)

// ---------------------------------------------------------------------------
// Warp MMA helpers (sm_80+ PTX: compiles under plain compute_100)
// ---------------------------------------------------------------------------
__device__ __forceinline__ uint32_t smem_u32(const void* p) {
    uint32_t a;
    asm("{ .reg .u64 t; cvta.to.shared.u64 t, %1; cvt.u32.u64 %0, t; }" : "=r"(a) : "l"(p));
    return a;
}
__device__ __forceinline__ void ldsm4(uint32_t& r0, uint32_t& r1, uint32_t& r2, uint32_t& r3,
                                      uint32_t addr) {
    asm volatile("ldmatrix.sync.aligned.m8n8.x4.shared.b16 {%0,%1,%2,%3}, [%4];"
                 : "=r"(r0), "=r"(r1), "=r"(r2), "=r"(r3) : "r"(addr));
}
__device__ __forceinline__ void mma16816(float* c, const uint32_t* a, const uint32_t* b) {
    asm volatile("mma.sync.aligned.m16n8k16.row.col.f32.bf16.bf16.f32 "
                 "{%0,%1,%2,%3}, {%4,%5,%6,%7}, {%8,%9}, {%0,%1,%2,%3};"
                 : "+f"(c[0]), "+f"(c[1]), "+f"(c[2]), "+f"(c[3])
                 : "r"(a[0]), "r"(a[1]), "r"(a[2]), "r"(a[3]), "r"(b[0]), "r"(b[1]));
}

// ---------------------------------------------------------------------------
// Scratch (device globals; no allocation allowed)
// ---------------------------------------------------------------------------
__device__ float4 g_Bimg[8192];    // pre-swizzled bf16 B image: [hi 64KB][lo 64KB]
__device__ float  g_wx[128];       // Wg[d*385+384]
__device__ float  g_cbuf[256*128]; // c[b,d] = (emb @ We^T)[b,d] + bg[d]

// SMEM layout of main kernel (relative to 1024-aligned base)
// B rows: d (128 rows x 512B = 256 bf16 k).  A rows: m (130 rows x 256B = 128 bf16 d).
// Swizzle: 16B-chunk index cc -> cc ^ (row & 7)   (xor affects low 3 bits only)
#define OFF_B    0          // B hi 65536 then B lo 65536
#define OFF_AH   131072     // A hi: 130 rows x 256B = 33280
#define OFF_AL   164352     // A lo: 33280
#define OFF_CB   197632     // c[b,d] f32 (512B)
#define OFF_WX   198144     // wx f32 (512B)
#define SMEM_MAIN (198656 + 1024)

// ---------------------------------------------------------------------------
// prep: build pre-swizzled bf16 hi/lo B image, extract wx, logdet output
// grid: 129 blocks x 256 threads
// ---------------------------------------------------------------------------
__global__ void prep_kernel(const float* __restrict__ Wg, float* __restrict__ out)
{
    if (blockIdx.x < 128) {
        int idx = blockIdx.x * 256 + threadIdx.x;   // 0..32767
        int d = idx >> 8;          // 0..127 (N row)
        int k = idx & 255;         // 0..255 (K col)
        float v = Wg[d * FF + 128 + k];
        __nv_bfloat16 hi = __float2bfloat16(v);
        __nv_bfloat16 lo = __float2bfloat16(v - __bfloat162float(hi));
        uint32_t cc = (uint32_t)(k >> 3);
        uint32_t off = (uint32_t)d * 512 + ((cc ^ (uint32_t)(d & 7)) << 4) + ((k & 7) << 1);
        char* base = (char*)g_Bimg;
        *(__nv_bfloat16*)(base + off) = hi;
        *(__nv_bfloat16*)(base + 65536 + off) = lo;
    } else {
        __shared__ float red[128];
        __shared__ float tot;
        int t = threadIdx.x;
        if (t < 128) {
            float w = Wg[t * FF + 384];
            g_wx[t] = w;
            red[t] = logf(fabsf(w));
        }
        __syncthreads();
        #pragma unroll
        for (int s = 64; s > 0; s >>= 1) {
            if (t < s) red[t] += red[t + s];
            __syncthreads();
        }
        if (t == 0) tot = red[0] * 510.0f;
        __syncthreads();
        out[RES_SIZE + t] = tot;   // one value per batch row
    }
}

// ---------------------------------------------------------------------------
// mlp: per-batch-row 3-layer MLP (leaky_relu 0.2) + c = emb @ We^T + bg
// grid: 256 blocks x 128 threads
// ---------------------------------------------------------------------------
__global__ void mlp_kernel(const float* __restrict__ emb_in,
                           const float* __restrict__ W1, const float* __restrict__ b1,
                           const float* __restrict__ W2, const float* __restrict__ b2,
                           const float* __restrict__ W3, const float* __restrict__ b3,
                           const float* __restrict__ Wg, const float* __restrict__ bg)
{
    extern __shared__ float sm[];
    float* Wsm = sm;             // 128 rows, pitch 129
    float* es  = sm + 128*129;
    const int b = blockIdx.x;
    const int t = threadIdx.x;

    es[t] = emb_in[b * 128 + t];

    #pragma unroll 4
    for (int i = 0; i < 128; i++) Wsm[i*129 + t] = W1[i*128 + t];
    __syncthreads();
    float acc = b1[t];
    #pragma unroll
    for (int k = 0; k < 128; k++) acc += es[k] * Wsm[t*129 + k];
    acc = (acc > 0.f) ? acc : 0.2f * acc;
    __syncthreads();
    es[t] = acc;

    #pragma unroll 4
    for (int i = 0; i < 128; i++) Wsm[i*129 + t] = W2[i*128 + t];
    __syncthreads();
    acc = b2[t];
    #pragma unroll
    for (int k = 0; k < 128; k++) acc += es[k] * Wsm[t*129 + k];
    acc = (acc > 0.f) ? acc : 0.2f * acc;
    __syncthreads();
    es[t] = acc;

    #pragma unroll 4
    for (int i = 0; i < 128; i++) Wsm[i*129 + t] = W3[i*128 + t];
    __syncthreads();
    acc = b3[t];
    #pragma unroll
    for (int k = 0; k < 128; k++) acc += es[k] * Wsm[t*129 + k];
    __syncthreads();
    es[t] = acc;

    #pragma unroll 4
    for (int i = 0; i < 128; i++) Wsm[i*129 + t] = Wg[i*FF + t];
    __syncthreads();
    float c = bg[t];
    #pragma unroll
    for (int k = 0; k < 128; k++) c += es[k] * Wsm[t*129 + k];
    g_cbuf[b * 128 + t] = c;
}

// ---------------------------------------------------------------------------
// main: split-bf16 mma.sync GEMM
// res[b,t,d] = c[b,d] + sum_k x[b,t,k]*Wy[d,k] + sum_k x[b,t+1,k]*Wy[d,128+k]
//            + x[b,t+2,d]*wx[d]
// grid: 1024 blocks (b = blk>>2, t-tile = blk&3) x 256 threads (8 warps, 4m x 2n)
// ---------------------------------------------------------------------------
__global__ void __launch_bounds__(256, 1)
main_kernel(const float* __restrict__ x, float* __restrict__ out)
{
    extern __shared__ char raw_sm[];
    char* sbc = (char*)(((uintptr_t)raw_sm + 1023) & ~(uintptr_t)1023);
    const uint32_t sb = smem_u32(sbc);

    const int bid = blockIdx.x;
    const int b   = bid >> 2;
    const int t0  = (bid & 3) * 128;
    const int TMloc = min(128, TMDIM - t0);     // 128,128,128,126
    const int nrows = min(130, TT - t0);        // 130,130,130,128
    const int tid  = threadIdx.x;
    const int wid  = tid >> 5;
    const int lane = tid & 31;

    // ---- stage B image (pre-swizzled, L2-hot) ----
    {
        float4* dst = (float4*)(sbc + OFF_B);
        #pragma unroll
        for (int i = 0; i < 32; i++) dst[i * 256 + tid] = g_Bimg[i * 256 + tid];
    }
    // ---- load x rows, split to bf16 hi/lo, swizzled store (16B chunks) ----
    {
        const float* xb = x + ((size_t)b * TT + t0) * DD;
        for (int idx = tid; idx < 130 * 16; idx += 256) {
            int m  = idx >> 4;      // 0..129
            int cc = idx & 15;      // 16B chunk within 256B row
            float4 v0 = make_float4(0.f, 0.f, 0.f, 0.f);
            float4 v1 = v0;
            if (m < nrows) {
                const float* src = xb + m * 128 + cc * 8;
                v0 = *(const float4*)(src);
                v1 = *(const float4*)(src + 4);
            }
            __nv_bfloat162 h01 = __floats2bfloat162_rn(v0.x, v0.y);
            __nv_bfloat162 h23 = __floats2bfloat162_rn(v0.z, v0.w);
            __nv_bfloat162 h45 = __floats2bfloat162_rn(v1.x, v1.y);
            __nv_bfloat162 h67 = __floats2bfloat162_rn(v1.z, v1.w);
            float2 f01 = __bfloat1622float2(h01), f23 = __bfloat1622float2(h23);
            float2 f45 = __bfloat1622float2(h45), f67 = __bfloat1622float2(h67);
            __nv_bfloat162 l01 = __floats2bfloat162_rn(v0.x - f01.x, v0.y - f01.y);
            __nv_bfloat162 l23 = __floats2bfloat162_rn(v0.z - f23.x, v0.w - f23.y);
            __nv_bfloat162 l45 = __floats2bfloat162_rn(v1.x - f45.x, v1.y - f45.y);
            __nv_bfloat162 l67 = __floats2bfloat162_rn(v1.z - f67.x, v1.w - f67.y);
            uint4 H, L;
            H.x = *(uint32_t*)&h01; H.y = *(uint32_t*)&h23;
            H.z = *(uint32_t*)&h45; H.w = *(uint32_t*)&h67;
            L.x = *(uint32_t*)&l01; L.y = *(uint32_t*)&l23;
            L.z = *(uint32_t*)&l45; L.w = *(uint32_t*)&l67;
            uint32_t off = (uint32_t)m * 256 + (((uint32_t)cc ^ (uint32_t)(m & 7)) << 4);
            *(uint4*)(sbc + OFF_AH + off) = H;
            *(uint4*)(sbc + OFF_AL + off) = L;
        }
    }
    // ---- epilogue constants into smem ----
    if (tid < 128) {
        ((float*)(sbc + OFF_CB))[tid] = g_cbuf[b * 128 + tid];
        ((float*)(sbc + OFF_WX))[tid] = g_wx[tid];
    }
    __syncthreads();

    // ---- warp tiles: 4 m-warps x 2 n-warps; warp = 32m x 64n ----
    const int m0 = (wid & 3) * 32;
    const int n0 = (wid >> 2) * 64;

    // ldmatrix lane roles
    const int rowoffA = (lane & 7) + (((lane >> 3) & 1) << 3);  // A: row within 16-tile
    const int khvA    = (lane >> 4) & 1;                        // A: k-half (x8)
    const int doffB   = (lane & 7) + (((lane >> 4) & 1) << 3);  // B: d within 16-group
    const int khvB    = (lane >> 3) & 1;                        // B: k-half (x8)
    const int la7     = lane & 7;

    const uint32_t Ah = sb + OFF_AH, Al = sb + OFF_AL;
    const uint32_t Bh = sb + OFF_B,  Bl = sb + OFF_B + 65536;

    float acc[2][8][4];
    #pragma unroll
    for (int f = 0; f < 2; f++)
        #pragma unroll
        for (int q = 0; q < 8; q++)
            #pragma unroll
            for (int i = 0; i < 4; i++) acc[f][q][i] = 0.f;

    #pragma unroll 1
    for (int term = 0; term < 3; term++) {
        const uint32_t Ab = (term == 2) ? Al : Ah;
        const uint32_t Bb = (term == 1) ? Bl : Bh;
        uint32_t bBase[4];
        #pragma unroll
        for (int q4 = 0; q4 < 4; q4++)
            bBase[q4] = Bb + (uint32_t)(n0 + q4 * 16 + doffB) * 512;
        #pragma unroll 1
        for (int l = 0; l < 2; l++) {
            const int rA0 = m0 + l + rowoffA;
            const uint32_t baseA0 = Ab + (uint32_t)rA0 * 256;
            const uint32_t baseA1 = baseA0 + 16 * 256;
            const int r7a = rA0 & 7;
            #pragma unroll
            for (int s = 0; s < 8; s++) {
                const uint32_t swzA = (uint32_t)((s * 2 + khvA) ^ r7a) << 4;
                uint32_t a[8];
                ldsm4(a[0], a[1], a[2], a[3], baseA0 + swzA);
                ldsm4(a[4], a[5], a[6], a[7], baseA1 + swzA);
                const uint32_t swzB = (uint32_t)((l * 16 + s * 2 + khvB) ^ la7) << 4;
                uint32_t bf[16];
                #pragma unroll
                for (int q4 = 0; q4 < 4; q4++)
                    ldsm4(bf[q4*4], bf[q4*4+1], bf[q4*4+2], bf[q4*4+3], bBase[q4] + swzB);
                #pragma unroll
                for (int f = 0; f < 2; f++)
                    #pragma unroll
                    for (int q = 0; q < 8; q++)
                        mma16816(acc[f][q], a + f * 4, bf + (q >> 1) * 4 + (q & 1) * 2);
            }
        }
    }

    // ---- epilogue: acc + c[b,d] + x[b,t+2,d]*wx[d] -> gmem ----
    {
        const float* scb = (const float*)(sbc + OFF_CB);
        const float* swx = (const float*)(sbc + OFF_WX);
        const int colq = 2 * (lane & 3);
        const int rbase = m0 + (lane >> 2);
        float* ob = out + ((size_t)b * TMDIM + t0) * DD;
        #pragma unroll
        for (int q = 0; q < 8; q++) {
            const int col = n0 + q * 8 + colq;
            const float2 cb = *(const float2*)(scb + col);
            const float2 wv = *(const float2*)(swx + col);
            const int ccx = col >> 3;
            #pragma unroll
            for (int f = 0; f < 2; f++) {
                #pragma unroll
                for (int h = 0; h < 2; h++) {
                    const int rr = rbase + 16 * f + 8 * h;
                    if (rr < TMloc) {
                        const int rx = rr + 2;
                        const uint32_t xoff = (uint32_t)rx * 256 +
                            (((uint32_t)ccx ^ (uint32_t)(rx & 7)) << 4) + (uint32_t)colq * 2;
                        float2 xh = __bfloat1622float2(*(const __nv_bfloat162*)(sbc + OFF_AH + xoff));
                        float2 xl = __bfloat1622float2(*(const __nv_bfloat162*)(sbc + OFF_AL + xoff));
                        float2 o;
                        o.x = acc[f][q][2*h]   + cb.x + (xh.x + xl.x) * wv.x;
                        o.y = acc[f][q][2*h+1] + cb.y + (xh.y + xl.y) * wv.y;
                        *(float2*)(ob + (size_t)rr * DD + col) = o;
                    }
                }
            }
        }
    }
}

// ---------------------------------------------------------------------------
extern "C" void kernel_launch(void* const* d_in, const int* in_sizes, int n_in,
                              void* d_out, int out_size)
{
    const float* x   = (const float*)d_in[0];
    const float* emb = (const float*)d_in[1];
    const float* W1  = (const float*)d_in[2];
    const float* b1  = (const float*)d_in[3];
    const float* W2  = (const float*)d_in[4];
    const float* b2  = (const float*)d_in[5];
    const float* W3  = (const float*)d_in[6];
    const float* b3  = (const float*)d_in[7];
    const float* Wg  = (const float*)d_in[8];
    const float* bg  = (const float*)d_in[9];
    float* out = (float*)d_out;

    const int mlp_smem = (128*129 + 128) * sizeof(float);
    cudaFuncSetAttribute(mlp_kernel,  cudaFuncAttributeMaxDynamicSharedMemorySize, mlp_smem);
    cudaFuncSetAttribute(main_kernel, cudaFuncAttributeMaxDynamicSharedMemorySize, SMEM_MAIN);

    prep_kernel<<<129, 256>>>(Wg, out);
    mlp_kernel<<<256, 128, mlp_smem>>>(emb, W1, b1, W2, b2, W3, b3, Wg, bg);
    main_kernel<<<1024, 256, SMEM_MAIN>>>(x, out);
}